// round 1
// baseline (speedup 1.0000x reference)
#include <cuda_runtime.h>

namespace {
constexpr int  Bc   = 8;
constexpr int  CIN  = 16;
constexpr int  COUT = 16;
constexpr int  KS   = 4;
constexpr long long NN = 524288;   // N
constexpr int  NQ   = 131072;      // N/4 quads, = 2^17
constexpr int  THREADS = 128;
}

// Packed fp32x2 FMA / MUL (Blackwell sm_100a; PTX-only, ptxas never auto-fuses)
__device__ __forceinline__ unsigned long long fma2(unsigned long long a,
                                                   unsigned long long b,
                                                   unsigned long long c) {
    unsigned long long d;
    asm("fma.rn.f32x2 %0, %1, %2, %3;" : "=l"(d) : "l"(a), "l"(b), "l"(c));
    return d;
}
__device__ __forceinline__ unsigned long long mul2(unsigned long long a,
                                                   unsigned long long b) {
    unsigned long long d;
    asm("mul.rn.f32x2 %0, %1, %2;" : "=l"(d) : "l"(a), "l"(b));
    return d;
}

__global__ __launch_bounds__(THREADS)
void tconv_f32x2_kernel(const float* __restrict__ inp,   // [B, CIN, N]
                        const float* __restrict__ wgt,   // [COUT, KS, CIN]
                        const float* __restrict__ att,   // [B, KS, N]
                        float* __restrict__ out)         // [B, COUT, N]
{
    // Weight staged in SMEM as duplicated (w,w) 64-bit pairs, re-indexed [k][o][c]
    // so the inner loops read it with warp-uniform addresses (broadcast LDS.64,
    // zero bank conflicts, no per-use packing instruction).
    __shared__ unsigned long long wdup[KS * COUT * CIN];
    const int tid = threadIdx.x;
    #pragma unroll
    for (int i = tid; i < KS * COUT * CIN; i += THREADS) {
        int k = i >> 8, o = (i >> 4) & 15, c = i & 15;
        unsigned int bits = __float_as_uint(wgt[(o * KS + k) * CIN + c]);
        wdup[i] = ((unsigned long long)bits << 32) | bits;
    }
    __syncthreads();

    const int idx = blockIdx.x * THREADS + tid;     // one thread = one (b, n-quad)
    const int b   = idx >> 17;                      // NQ = 2^17
    const long long n4 = (long long)(idx & (NQ - 1)) << 2;

    const float* xb = inp + (long long)b * CIN * NN + n4;
    const float* sb = att + (long long)b * KS  * NN + n4;
    float*       ob = out + (long long)b * COUT * NN + n4;

    // Load 4 n's of all 16 channels + 4 score taps as packed f32x2 pairs.
    unsigned long long xlo[CIN], xhi[CIN];
    #pragma unroll
    for (int c = 0; c < CIN; c++) {
        ulonglong2 v = *reinterpret_cast<const ulonglong2*>(xb + (long long)c * NN);
        xlo[c] = v.x; xhi[c] = v.y;
    }
    unsigned long long slo[KS], shi[KS];
    #pragma unroll
    for (int k = 0; k < KS; k++) {
        ulonglong2 v = *reinterpret_cast<const ulonglong2*>(sb + (long long)k * NN);
        slo[k] = v.x; shi[k] = v.y;
    }

    // Output channels processed in two halves of 8 to bound register pressure.
    #pragma unroll
    for (int h = 0; h < 2; ++h) {
        unsigned long long alo[8], ahi[8];
        #pragma unroll
        for (int o = 0; o < 8; o++) { alo[o] = 0ull; ahi[o] = 0ull; }

        #pragma unroll
        for (int k = 0; k < KS; k++) {
            #pragma unroll
            for (int c = 0; c < CIN; c++) {
                // z[k][c] = x[c] * s[k], packed over 4 n's
                unsigned long long zl = mul2(xlo[c], slo[k]);
                unsigned long long zh = mul2(xhi[c], shi[k]);
                const unsigned long long* wrow =
                    &wdup[(k * COUT + h * 8) * CIN + c];
                #pragma unroll
                for (int o = 0; o < 8; o++) {
                    unsigned long long w = wrow[o * CIN];
                    alo[o] = fma2(w, zl, alo[o]);
                    ahi[o] = fma2(w, zh, ahi[o]);
                }
            }
        }

        #pragma unroll
        for (int o = 0; o < 8; o++) {
            ulonglong2 r; r.x = alo[o]; r.y = ahi[o];
            *reinterpret_cast<ulonglong2*>(ob + (long long)(h * 8 + o) * NN) = r;
        }
    }
}

extern "C" void kernel_launch(void* const* d_in, const int* in_sizes, int n_in,
                              void* d_out, int out_size)
{
    const float* inp = (const float*)d_in[0];   // input  [8,16,524288]
    const float* wgt = (const float*)d_in[1];   // weight [16,4,16]
    const float* att = (const float*)d_in[2];   // attention_score [8,4,524288]
    float* out = (float*)d_out;                 // [8,16,524288]

    const int total_threads = Bc * NQ;          // 1,048,576
    tconv_f32x2_kernel<<<total_threads / THREADS, THREADS>>>(inp, wgt, att, out);
}